// round 8
// baseline (speedup 1.0000x reference)
#include <cuda_runtime.h>
#include <stdint.h>

#define IN_DIM   4096
#define OUT_DIM  1024
#define RB       128     // x rows per block (4 per lane: 4L..4L+3)
#define KT       256     // K columns per phase
#define NPH      16      // IN_DIM / KT
#define TPB      1024
#define OPW      8       // outputs per warp
#define OSPLIT   4       // output groups
#define OPB      (OUT_DIM / OSPLIT)   // 256 outputs per block
#define NSLICE   (NPH * OSPLIT)       // 64 (phase, outgroup) slices
#define SLICE_CAP 1024   // entries per slice (avg ~640, sigma ~25)
#define CSTRIDE_B 528    // bytes per tile column (132 floats, 16B aligned)
#define TILE_BYTES (KT * CSTRIDE_B)            // 135168
#define TAB_OFF   TILE_BYTES                   // int2 staged table
#define OFF_OFF   (TAB_OFF + SLICE_CAP * 8)    // 143360, 16B aligned
#define SMEM_BYTES (OFF_OFF + (OPB + 1) * 4)   // 144388
#define OSTRIDE   260    // floats, output staging stride (1040B, 16B aligned)

// Phase-major packed sparse table (rebuilt every launch; deterministic).
// Slice s = p*OSPLIT + og: entries of phase p for outputs [og*256, og*256+256).
// Entry = { byte offset (c_local * 528) within the column-major tile, fp32 bits }.
__device__ int  g_cnt[NPH * OUT_DIM];
__device__ int  g_soff[NSLICE][OPB + 1];
__device__ int2 g_ptab[NSLICE * SLICE_CAP];

// ---------------------------------------------------------------------------
// Prep 1: nonzero count per (output o, phase q). Warp q owns cols [q*256, +256).
// ---------------------------------------------------------------------------
__global__ void __launch_bounds__(512) count_kernel(const float* __restrict__ Phi) {
    const int o = blockIdx.x, t = threadIdx.x, q = t >> 5, u = t & 31;
    const float* row = Phi + (size_t)o * IN_DIM;
    int cnt = 0;
#pragma unroll
    for (int k = 0; k < 8; k++) cnt += (row[q * KT + k * 32 + u] != 0.0f);
#pragma unroll
    for (int d = 16; d; d >>= 1) cnt += __shfl_down_sync(0xffffffffu, cnt, d);
    if (u == 0) g_cnt[q * OUT_DIM + o] = cnt;
}

// ---------------------------------------------------------------------------
// Prep 2: exclusive scan of counts within each (phase, outgroup) slice.
// ---------------------------------------------------------------------------
__global__ void __launch_bounds__(OPB) scan_kernel() {
    const int s = blockIdx.x;              // s = p*OSPLIT + og
    const int p = s >> 2, og = s & 3, t = threadIdx.x;
    __shared__ int sh[OPB];
    int c = g_cnt[p * OUT_DIM + og * OPB + t];
    sh[t] = c;
    __syncthreads();
#pragma unroll
    for (int d = 1; d < OPB; d <<= 1) {
        int v = (t >= d) ? sh[t - d] : 0;
        __syncthreads();
        sh[t] += v;
        __syncthreads();
    }
    g_soff[s][t] = min(sh[t] - c, SLICE_CAP);
    if (t == OPB - 1) g_soff[s][OPB] = min(sh[t], SLICE_CAP);
}

// ---------------------------------------------------------------------------
// Prep 3: fill packed table (deterministic lane-k order), no padding.
// ---------------------------------------------------------------------------
__global__ void __launch_bounds__(512) fill_kernel(const float* __restrict__ Phi) {
    const int o = blockIdx.x, t = threadIdx.x, q = t >> 5, u = t & 31;
    const int og = o >> 8;                 // o / OPB
    const int ol = o & (OPB - 1);
    const int s  = q * OSPLIT + og;
    const float* row = Phi + (size_t)o * IN_DIM;

    float rv[8];
    int cnt = 0;
#pragma unroll
    for (int k = 0; k < 8; k++) { rv[k] = row[q * KT + k * 32 + u]; cnt += (rv[k] != 0.0f); }

    int ex = cnt;
#pragma unroll
    for (int d = 1; d < 32; d <<= 1) {
        int v = __shfl_up_sync(0xffffffffu, ex, d);
        if (u >= d) ex += v;
    }
    ex -= cnt;   // exclusive prefix over lanes

    int dst = g_soff[s][ol] + ex;
#pragma unroll
    for (int k = 0; k < 8; k++) {
        float v = rv[k];
        if (v != 0.0f) {
            if (dst < SLICE_CAP) {
                int c_local = k * 32 + u;   // column within phase, 0..255
                g_ptab[s * SLICE_CAP + dst] =
                    make_int2(c_local * CSTRIDE_B, __float_as_int(v));
            }
            dst++;
        }
    }
}

// ---------------------------------------------------------------------------
// Main: sparse out = x @ Phi^T. Block: 128 x-rows (lane L -> rows 4L..4L+3),
// 256 outputs (warp w -> 8 contiguous), 16 K-phases of 256 cols.
// x tile is COLUMN-MAJOR: one warp-uniform entry -> one LDS.128 -> 4 FFMA.
// blockIdx: low 2 bits = output group (4 siblings share x rows -> L2 reuse).
// ---------------------------------------------------------------------------
__global__ void __launch_bounds__(TPB, 1) spjl_kernel(
    const float* __restrict__ x, float* __restrict__ out, int nrows) {
    extern __shared__ float xs[];                          // column-major x tile
    int2* st_tab = (int2*)((char*)xs + TAB_OFF);
    int*  st_off = (int*)((char*)xs + OFF_OFF);

    const int tid = threadIdx.x;
    const int w   = tid >> 5;
    const int L   = tid & 31;
    const int rg  = blockIdx.x >> 2;
    const int og  = blockIdx.x & 3;
    const size_t n0 = (size_t)rg * RB;
    const int olb = w * OPW;                               // warp's first local output

    float acc[OPW][4];
#pragma unroll
    for (int io = 0; io < OPW; io++)
#pragma unroll
        for (int j = 0; j < 4; j++) acc[io][j] = 0.0f;

    const char* xgrp = (const char*)xs + L * 16;           // lane's 4-row group base

    for (int p = 0; p < NPH; p++) {
        const int s = p * OSPLIT + og;
        const int len = g_soff[s][OPB];
        __syncthreads();   // previous phase readers done before overwrite

        // Stage x tile column-major: unit = 4 rows x 1 col per thread-iter.
        // LDG scalar coalesced (warp covers 32 consecutive cols of one row);
        // STS.128 conflict-free (bank = 4c + const, 8 lanes/phase span all 32).
#pragma unroll
        for (int it = 0; it < (RB * KT / 4) / TPB; it++) {
            int un = tid + it * TPB;
            int g  = un >> 8;             // row group 0..31
            int c  = un & (KT - 1);       // column 0..255
            size_t gr0 = n0 + 4 * g;
            const float* xp = x + gr0 * IN_DIM + (size_t)p * KT + c;
            float v0 = 0.0f, v1 = 0.0f, v2 = 0.0f, v3 = 0.0f;
            if (gr0 + 3 < (size_t)nrows) {
                v0 = xp[0]; v1 = xp[IN_DIM]; v2 = xp[2 * IN_DIM]; v3 = xp[3 * IN_DIM];
            } else {
                if (gr0 + 0 < (size_t)nrows) v0 = xp[0];
                if (gr0 + 1 < (size_t)nrows) v1 = xp[IN_DIM];
                if (gr0 + 2 < (size_t)nrows) v2 = xp[2 * IN_DIM];
                if (gr0 + 3 < (size_t)nrows) v3 = xp[3 * IN_DIM];
            }
            *(float4*)((char*)xs + c * CSTRIDE_B + g * 16) = make_float4(v0, v1, v2, v3);
        }
        // Stage table slice + offsets (coalesced).
        if (tid <= OPB) st_off[tid] = g_soff[s][tid];
        for (int i = tid; i < len; i += TPB) st_tab[i] = g_ptab[s * SLICE_CAP + i];
        __syncthreads();

        // Bounds preloaded into registers (warp-uniform).
        int4 B0 = *(const int4*)(st_off + olb);
        int4 B1 = *(const int4*)(st_off + olb + 4);
        int  e8 = st_off[olb + 8];
        int Bb[OPW + 1] = {B0.x, B0.y, B0.z, B0.w, B1.x, B1.y, B1.z, B1.w, e8};

#pragma unroll
        for (int io = 0; io < OPW; io++) {
            const int jb = Bb[io], je = Bb[io + 1];
            float a0 = acc[io][0], a1 = acc[io][1], a2 = acc[io][2], a3 = acc[io][3];
            for (int j = jb; j < je; j++) {
                int2 e = st_tab[j];                        // warp-uniform broadcast
                float phv = __int_as_float(e.y);
                float4 xv = *(const float4*)(xgrp + e.x);  // 4 rows, conflict-free
                a0 = fmaf(phv, xv.x, a0);
                a1 = fmaf(phv, xv.y, a1);
                a2 = fmaf(phv, xv.z, a2);
                a3 = fmaf(phv, xv.w, a3);
            }
            acc[io][0] = a0; acc[io][1] = a1; acc[io][2] = a2; acc[io][3] = a3;
        }
    }

    __syncthreads();
    // Stage results row-major (stride OSTRIDE) in the tile area, then coalesced STG.
#pragma unroll
    for (int io = 0; io < OPW; io++)
#pragma unroll
        for (int j = 0; j < 4; j++)
            xs[(4 * L + j) * OSTRIDE + olb + io] = acc[io][j];
    __syncthreads();
#pragma unroll
    for (int it = 0; it < (RB * OPB / 4) / TPB; it++) {
        int i4  = tid + it * TPB;
        int row = i4 >> 6;                 // 64 float4 per row
        int c4  = i4 & 63;
        size_t gr = n0 + row;
        if (gr < (size_t)nrows) {
            float4 v = *(const float4*)(xs + row * OSTRIDE + c4 * 4);
            *(float4*)(out + gr * OUT_DIM + og * OPB + c4 * 4) = v;
        }
    }
}

extern "C" void kernel_launch(void* const* d_in, const int* in_sizes, int n_in,
                              void* d_out, int out_size) {
    const float* x   = (const float*)d_in[0];   // [N, 4096] fp32
    const float* Phi = (const float*)d_in[1];   // [1024, 4096] fp32
    float* out = (float*)d_out;                 // [N, 1024] fp32

    const int nrows = in_sizes[0] / IN_DIM;              // 16384
    const int grid  = ((nrows + RB - 1) / RB) * OSPLIT;  // 512

    cudaFuncSetAttribute(spjl_kernel,
                         cudaFuncAttributeMaxDynamicSharedMemorySize, SMEM_BYTES);

    count_kernel<<<OUT_DIM, 512>>>(Phi);
    scan_kernel<<<NSLICE, OPB>>>();
    fill_kernel<<<OUT_DIM, 512>>>(Phi);
    spjl_kernel<<<grid, TPB, SMEM_BYTES>>>(x, out, nrows);
}

// round 13
// speedup vs baseline: 1.5291x; 1.5291x over previous
#include <cuda_runtime.h>
#include <stdint.h>

#define IN_DIM   4096
#define OUT_DIM  1024
#define RB       32          // x rows per block (1 per lane)
#define KT       1024        // K columns per phase
#define NPH      4           // IN_DIM / KT
#define TPB      1024
#define OPW      32          // outputs per warp (all 1024 outputs per block)
#define SLICE_CAP 11264      // exact bound: 1024 cols * 10 nnz + <=1024 pad
#define XS_STRIDE 1025       // floats; bank = (row + col) % 32 -> conflict-free
#define ROW_BYTES (XS_STRIDE * 4)              // 4100
#define TAB_OFF   (RB * XS_STRIDE * 4)         // 131200 (16B aligned)
#define OFF_OFF   (TAB_OFF + SLICE_CAP * 8)    // 221312 (16B aligned)
#define SMEM_BYTES (OFF_OFF + (OUT_DIM + 4) * 4)   // 225424

// Phase-major packed table (rebuilt every launch; deterministic).
// g_ptab[p]: entries of phase p for ALL 1024 outputs, segments contiguous and
// padded to EVEN length with null (0, 0.0f) entries -> int4 (2-entry) aligned.
// Entry = { byte offset of col within phase (c_local*4), fp32 value bits }.
__device__ int  g_cnt[NPH][OUT_DIM];           // padded (even) counts
__device__ int  g_soff[NPH][OUT_DIM + 1];      // exclusive scan per phase
__device__ int2 g_ptab[NPH][SLICE_CAP];

// ---------------------------------------------------------------------------
// Prep 1: padded nonzero count per (output o, phase q). Warp q owns
// cols [q*1024, (q+1)*1024); coalesced reads.
// ---------------------------------------------------------------------------
__global__ void __launch_bounds__(128) count_kernel(const float* __restrict__ Phi) {
    const int o = blockIdx.x, t = threadIdx.x, q = t >> 5, u = t & 31;
    const float* row = Phi + (size_t)o * IN_DIM;
    int cnt = 0;
#pragma unroll
    for (int k = 0; k < 32; k++) cnt += (row[q * KT + k * 32 + u] != 0.0f);
#pragma unroll
    for (int d = 16; d; d >>= 1) cnt += __shfl_down_sync(0xffffffffu, cnt, d);
    if (u == 0) g_cnt[q][o] = (cnt + 1) & ~1;   // pad to even
}

// ---------------------------------------------------------------------------
// Prep 2: exclusive scan of padded counts within each phase.
// ---------------------------------------------------------------------------
__global__ void __launch_bounds__(OUT_DIM) scan_kernel() {
    const int p = blockIdx.x, t = threadIdx.x;
    __shared__ int sh[OUT_DIM];
    int c = g_cnt[p][t];
    sh[t] = c;
    __syncthreads();
#pragma unroll
    for (int d = 1; d < OUT_DIM; d <<= 1) {
        int v = (t >= d) ? sh[t - d] : 0;
        __syncthreads();
        sh[t] += v;
        __syncthreads();
    }
    g_soff[p][t] = min(sh[t] - c, SLICE_CAP);
    if (t == OUT_DIM - 1) g_soff[p][OUT_DIM] = min(sh[t], SLICE_CAP);
}

// ---------------------------------------------------------------------------
// Prep 3: fill packed table (deterministic lane-k order) + null padding.
// ---------------------------------------------------------------------------
__global__ void __launch_bounds__(128) fill_kernel(const float* __restrict__ Phi) {
    const int o = blockIdx.x, t = threadIdx.x, q = t >> 5, u = t & 31;
    const float* row = Phi + (size_t)o * IN_DIM;

    float rv[32];
    int cnt = 0;
#pragma unroll
    for (int k = 0; k < 32; k++) { rv[k] = row[q * KT + k * 32 + u]; cnt += (rv[k] != 0.0f); }

    int ex = cnt;
#pragma unroll
    for (int d = 1; d < 32; d <<= 1) {
        int v = __shfl_up_sync(0xffffffffu, ex, d);
        if (u >= d) ex += v;
    }
    int tot = __shfl_sync(0xffffffffu, ex, 31);   // inclusive total
    ex -= cnt;                                    // exclusive prefix

    const int base = g_soff[q][o];
    int dst = base + ex;
#pragma unroll
    for (int k = 0; k < 32; k++) {
        float v = rv[k];
        if (v != 0.0f) {
            if (dst < SLICE_CAP)
                g_ptab[q][dst] = make_int2((k * 32 + u) * 4, __float_as_int(v));
            dst++;
        }
    }
    if (u == 0 && (tot & 1) && (base + tot) < SLICE_CAP)
        g_ptab[q][base + tot] = make_int2(0, 0);   // null pad -> harmless FMA
}

// ---------------------------------------------------------------------------
// Main: sparse out = x @ Phi^T. Block: 32 x-rows (lane L = row n0+L),
// ALL 1024 outputs (warp w -> 32), 4 K-phases of 1024 cols.
// Per phase the ENTIRE table slice (~88KB) + x tile (128KB) live in smem.
// Segments avg 10 entries; hot loop: LDS.128 tab (broadcast) -> 2 LDS + 2 FFMA.
// x is read from DRAM exactly once.
// ---------------------------------------------------------------------------
__global__ void __launch_bounds__(TPB, 1) spjl_kernel(
    const float* __restrict__ x, float* __restrict__ out, int nrows) {
    extern __shared__ float xs[];                       // x tile [32 * 1025]
    int2* st_tab = (int2*)((char*)xs + TAB_OFF);
    int*  st_off = (int*)((char*)xs + OFF_OFF);

    const int tid = threadIdx.x;
    const int w   = tid >> 5;
    const int L   = tid & 31;
    const size_t n0 = (size_t)blockIdx.x * RB;
    const int olb = w * OPW;                            // warp's first output

    float acc[OPW];
#pragma unroll
    for (int io = 0; io < OPW; io++) acc[io] = 0.0f;

    const char* xrow = (const char*)xs + L * ROW_BYTES;

    for (int p = 0; p < NPH; p++) {
        __syncthreads();   // previous phase readers done before overwrite

        // Stage x tile: 32 rows x 1024 cols (LDG.128 coalesced).
#pragma unroll
        for (int it = 0; it < (RB * KT / 4) / TPB; it++) {
            int idx = tid + it * TPB;
            int row = idx >> 8;            // 256 float4 per row
            int c4  = idx & 255;
            size_t gr = n0 + row;
            float4 v = make_float4(0.f, 0.f, 0.f, 0.f);
            if (gr < (size_t)nrows)
                v = *(const float4*)(x + gr * IN_DIM + (size_t)p * KT + c4 * 4);
            float* dst = xs + row * XS_STRIDE + c4 * 4;
            dst[0] = v.x; dst[1] = v.y; dst[2] = v.z; dst[3] = v.w;
        }
        // Stage full table slice (int4 copies) + offsets (coalesced).
        const int len = g_soff[p][OUT_DIM];             // padded total (even)
        {
            const int4* src = (const int4*)g_ptab[p];
            int4*       dst = (int4*)st_tab;
            for (int i = tid; i < (len >> 1); i += TPB) dst[i] = src[i];
        }
        st_off[tid] = g_soff[p][tid];
        if (tid == 0) st_off[OUT_DIM] = len;
        __syncthreads();

        int jb = st_off[olb];
#pragma unroll
        for (int io = 0; io < OPW; io++) {
            const int je = st_off[olb + io + 1];
            float a = acc[io];
            for (int j = jb; j < je; j += 2) {
                int4 e = *(const int4*)(st_tab + j);    // 2 entries, broadcast
                a = fmaf(__int_as_float(e.y), *(const float*)(xrow + e.x), a);
                a = fmaf(__int_as_float(e.w), *(const float*)(xrow + e.z), a);
            }
            acc[io] = a;
            jb = je;
        }
    }

    __syncthreads();
    // Stage results (alias x tile); bank = (L + col) % 32 -> conflict-free.
#pragma unroll
    for (int io = 0; io < OPW; io++)
        xs[L * XS_STRIDE + olb + io] = acc[io];
    __syncthreads();
    // Coalesced store of 32 rows x 1024 outputs.
#pragma unroll
    for (int it = 0; it < (RB * OUT_DIM) / TPB; it++) {
        int idx = tid + it * TPB;
        int row = idx >> 10;
        int c   = idx & (OUT_DIM - 1);
        size_t gr = n0 + row;
        if (gr < (size_t)nrows)
            out[gr * OUT_DIM + c] = xs[row * XS_STRIDE + c];
    }
}

extern "C" void kernel_launch(void* const* d_in, const int* in_sizes, int n_in,
                              void* d_out, int out_size) {
    const float* x   = (const float*)d_in[0];   // [N, 4096] fp32
    const float* Phi = (const float*)d_in[1];   // [1024, 4096] fp32
    float* out = (float*)d_out;                 // [N, 1024] fp32

    const int nrows = in_sizes[0] / IN_DIM;     // 16384
    const int grid  = (nrows + RB - 1) / RB;    // 512

    cudaFuncSetAttribute(spjl_kernel,
                         cudaFuncAttributeMaxDynamicSharedMemorySize, SMEM_BYTES);

    count_kernel<<<OUT_DIM, 128>>>(Phi);
    scan_kernel<<<NPH, OUT_DIM>>>();
    fill_kernel<<<OUT_DIM, 128>>>(Phi);
    spjl_kernel<<<grid, TPB, SMEM_BYTES>>>(x, out, nrows);
}